// round 2
// baseline (speedup 1.0000x reference)
#include <cuda_runtime.h>
#include <math_constants.h>

#define LEXP 64
#define KSEL 8
#define TM   64
#define HC   32
#define NTHREADS 256

// Global scratch (no allocations allowed): histogram + active-token count + mask dtype flag.
__device__ int g_hist[LEXP];
__device__ int g_active;
__device__ int g_mask32;   // 1 if mask buffer is 32-bit elements (int32/float32), 0 if bytes

__global__ void zero_kernel(const unsigned char* __restrict__ mask) {
    int t = threadIdx.x;
    if (t < LEXP) g_hist[t] = 0;
    if (t == 0) {
        g_active = 0;
        // Detect mask element width. Harness dtypes are {f32, i32, bf16}; bool
        // was likely widened to i32 (01 00 00 00) or f32 (00 00 80 3f). A real
        // u8 all-ones mask gives 01 01 ...
        const unsigned char b0 = mask[0];
        const unsigned char b1 = mask[1];
        g_mask32 = (b0 != 0 && b1 != 0) ? 0 : 1;
    }
}

__device__ __forceinline__ unsigned long long pack2(float lo, float hi) {
    unsigned long long r;
    asm("mov.b64 %0, {%1, %2};" : "=l"(r)
        : "r"(__float_as_uint(lo)), "r"(__float_as_uint(hi)));
    return r;
}

__device__ __forceinline__ void unpack2(unsigned long long v, float& lo, float& hi) {
    unsigned int a, b;
    asm("mov.b64 {%0, %1}, %2;" : "=r"(a), "=r"(b) : "l"(v));
    lo = __uint_as_float(a);
    hi = __uint_as_float(b);
}

// sm_103a packed dual-FMA (FFMA2): 2x fp32 FMA per instruction.
__device__ __forceinline__ unsigned long long ffma2(unsigned long long a,
                                                    unsigned long long b,
                                                    unsigned long long c) {
    unsigned long long d;
    asm("fma.rn.f32x2 %0, %1, %2, %3;" : "=l"(d) : "l"(a), "l"(b), "l"(c));
    return d;
}

__global__ void __launch_bounds__(NTHREADS, 2)
router_kernel(const float* __restrict__ x, const float* __restrict__ Wr,
              const float* __restrict__ bias, const unsigned char* __restrict__ mask,
              float* __restrict__ out_sel, float* __restrict__ out_prob,
              int M, int H)
{
    __shared__ __align__(16) float sx[HC][TM + 1];
    __shared__ __align__(16) float sw[HC][LEXP + 2];
    __shared__ __align__(16) float slog[TM][LEXP];
    __shared__ float sbias[LEXP];
    __shared__ int   shist[LEXP];
    __shared__ int   sactive;
    __shared__ int   smask32;

    const int tid = threadIdx.x;
    const int tokBase = blockIdx.x * TM;

    if (tid < LEXP) { sbias[tid] = bias[tid]; shist[tid] = 0; }
    if (tid == 0) { sactive = 0; smask32 = g_mask32; }

    // compute-tile mapping: 2 tokens x 8 experts (4 expert pairs) per thread
    const int tg = tid >> 3;        // 0..31
    const int eg = tid & 7;         // 0..7
    const int tok0 = tg * 2;
    const int e0 = eg * 8;

    // staging mapping: one row (token or expert) per 4 threads, 8 floats each
    const int lrow = tid >> 2;      // 0..63
    const int q = tid & 3;          // 0..3

    unsigned long long accA[4], accB[4];
#pragma unroll
    for (int p = 0; p < 4; ++p) { accA[p] = 0ULL; accB[p] = 0ULL; }

    for (int hb = 0; hb < H; hb += HC) {
        __syncthreads();
        // ---- stage x tile (64 tokens x 32 h), transposed to [h][tok] ----
        {
            const int gtok = tokBase + lrow;
            float4 f0, f1;
            if (gtok < M) {
                const float* src = x + (size_t)gtok * H + hb + q * 8;
                f0 = *(const float4*)src;
                f1 = *(const float4*)(src + 4);
            } else {
                f0 = make_float4(0.f, 0.f, 0.f, 0.f);
                f1 = f0;
            }
            const int h0 = q * 8;
            sx[h0 + 0][lrow] = f0.x; sx[h0 + 1][lrow] = f0.y;
            sx[h0 + 2][lrow] = f0.z; sx[h0 + 3][lrow] = f0.w;
            sx[h0 + 4][lrow] = f1.x; sx[h0 + 5][lrow] = f1.y;
            sx[h0 + 6][lrow] = f1.z; sx[h0 + 7][lrow] = f1.w;
        }
        // ---- stage W tile (64 experts x 32 h), transposed to [h][expert] ----
        {
            const float* src = Wr + (size_t)lrow * H + hb + q * 8;
            float4 f0 = *(const float4*)src;
            float4 f1 = *(const float4*)(src + 4);
            const int h0 = q * 8;
            sw[h0 + 0][lrow] = f0.x; sw[h0 + 1][lrow] = f0.y;
            sw[h0 + 2][lrow] = f0.z; sw[h0 + 3][lrow] = f0.w;
            sw[h0 + 4][lrow] = f1.x; sw[h0 + 5][lrow] = f1.y;
            sw[h0 + 6][lrow] = f1.z; sw[h0 + 7][lrow] = f1.w;
        }
        __syncthreads();

        // ---- FFMA2 mainloop ----
#pragma unroll
        for (int h = 0; h < HC; ++h) {
            const float xa = sx[h][tok0];
            const float xb = sx[h][tok0 + 1];
            const unsigned long long xpa = pack2(xa, xa);
            const unsigned long long xpb = pack2(xb, xb);
            const unsigned long long* wp =
                reinterpret_cast<const unsigned long long*>(&sw[h][e0]);
#pragma unroll
            for (int p = 0; p < 4; ++p) {
                const unsigned long long wv = wp[p];
                accA[p] = ffma2(xpa, wv, accA[p]);
                accB[p] = ffma2(xpb, wv, accB[p]);
            }
        }
    }

    // ---- logits to smem ----
#pragma unroll
    for (int p = 0; p < 4; ++p) {
        float lo, hi;
        unpack2(accA[p], lo, hi);
        slog[tok0][e0 + 2 * p]     = lo;
        slog[tok0][e0 + 2 * p + 1] = hi;
        unpack2(accB[p], lo, hi);
        slog[tok0 + 1][e0 + 2 * p]     = lo;
        slog[tok0 + 1][e0 + 2 * p + 1] = hi;
    }
    __syncthreads();

    // ---- epilogue: per-token top-8 (on logits+bias) + softmax over selected ----
    const int lane = tid & 31;
    const int wrp = tid >> 5;       // 8 warps, 8 tokens each
    const float NEG_INF = -CUDART_INF_F;
    const int mask32 = smask32;

    for (int tk = 0; tk < 8; ++tk) {
        const int tok = wrp * 8 + tk;
        const int gtok = tokBase + tok;
        if (gtok >= M) break;       // uniform within warp

        const float l0 = slog[tok][lane];
        const float l1 = slog[tok][lane + 32];
        float b0 = l0 + sbias[lane];
        float b1 = l1 + sbias[lane + 32];

        int   sel_idx = 0;
        float sel_logit = NEG_INF;

#pragma unroll
        for (int r = 0; r < KSEL; ++r) {
            float bv; int bi;
            if (b0 >= b1) { bv = b0; bi = lane; }       // tie -> lower index
            else          { bv = b1; bi = lane + 32; }
#pragma unroll
            for (int s = 16; s >= 1; s >>= 1) {
                const float ov = __shfl_xor_sync(0xffffffffu, bv, s);
                const int   oi = __shfl_xor_sync(0xffffffffu, bi, s);
                if (ov > bv || (ov == bv && oi < bi)) { bv = ov; bi = oi; }
            }
            if (lane == r) { sel_idx = bi; sel_logit = slog[tok][bi]; }
            if ((bi & 31) == lane) {                    // owner masks winner
                if (bi < 32) b0 = NEG_INF; else b1 = NEG_INF;
            }
        }

        // softmax over the 8 selected unbiased logits (full-softmax denom cancels)
        const float lv = (lane < KSEL) ? sel_logit : NEG_INF;
        float mval = lv;
#pragma unroll
        for (int s = 16; s >= 1; s >>= 1)
            mval = fmaxf(mval, __shfl_xor_sync(0xffffffffu, mval, s));
        const float ev = (lane < KSEL) ? __expf(lv - mval) : 0.f;
        float ssum = ev;
#pragma unroll
        for (int s = 16; s >= 1; s >>= 1)
            ssum += __shfl_xor_sync(0xffffffffu, ssum, s);

        // active-mask read, dtype-robust: 32-bit word nonzero covers int32(1)
        // and float32(1.0f); byte path covers a genuine u8 mask.
        bool act;
        if (mask32) {
            act = (((const unsigned int*)mask)[gtok] != 0u);
        } else {
            act = (mask[gtok] != 0);
        }

        if (lane < KSEL) {
            out_sel [(size_t)gtok * KSEL + lane] = (float)sel_idx;
            out_prob[(size_t)gtok * KSEL + lane] = ev / ssum;
            if (act) atomicAdd(&shist[sel_idx], 1);
        }
        if (lane == 0 && act) atomicAdd(&sactive, 1);
    }

    __syncthreads();
    if (tid < LEXP) atomicAdd(&g_hist[tid], shist[tid]);
    if (tid == 0) atomicAdd(&g_active, sactive);
}

__global__ void finalize_kernel(float* __restrict__ out_scal, int has_vio) {
    if (threadIdx.x == 0) {
        const float denom = (float)g_active * (float)KSEL;
        const float invL = 1.f / (float)LEXP;
        float s = 0.f, mx = -CUDART_INF_F;
        for (int l = 0; l < LEXP; ++l) {
            const float f = (float)g_hist[l] / denom;
            const float d = f - invL;
            s += d * d;
            mx = fmaxf(mx, d);
        }
        out_scal[0] = (float)LEXP * s;            // load_balance_loss
        if (has_vio) out_scal[1] = (float)LEXP * mx;  // max_vio
    }
}

extern "C" void kernel_launch(void* const* d_in, const int* in_sizes, int n_in,
                              void* d_out, int out_size) {
    const float* x    = (const float*)d_in[0];
    const float* Wr   = (const float*)d_in[1];
    const float* bias = (const float*)d_in[2];
    const unsigned char* mask = (const unsigned char*)d_in[3];

    const int L = in_sizes[2];          // 64
    const int H = in_sizes[1] / L;      // 2048
    const int M = in_sizes[0] / H;      // 16384 tokens (B*N)

    float* out = (float*)d_out;
    float* out_sel  = out;                          // (M, K) indices as float
    float* out_prob = out + (size_t)M * KSEL;       // (M, K) probs
    float* out_scal = out + (size_t)2 * M * KSEL;   // loss [, max_vio]
    const int has_vio = (out_size >= 2 * M * KSEL + 2) ? 1 : 0;

    zero_kernel<<<1, 64>>>(mask);
    const int grid = (M + TM - 1) / TM;
    router_kernel<<<grid, NTHREADS>>>(x, Wr, bias, mask, out_sel, out_prob, M, H);
    finalize_kernel<<<1, 32>>>(out_scal, has_vio);
}

// round 3
// speedup vs baseline: 1.5839x; 1.5839x over previous
#include <cuda_runtime.h>
#include <math_constants.h>

#define LEXP 64
#define KSEL 8
#define TM   64          // tokens per CTA
#define HC   32          // h-chunk staged in smem
#define NTHREADS 64      // one thread per (8-token x 8-expert) register tile
#define TT   8           // tokens per thread
#define TE   8           // experts per thread

// Global scratch: histogram + active-token count + mask dtype flag.
__device__ int g_hist[LEXP];
__device__ int g_active;
__device__ int g_mask32;   // 1 if mask is 32-bit elements (int32/float32), 0 if bytes

__global__ void zero_kernel(const unsigned char* __restrict__ mask) {
    int t = threadIdx.x;
    if (t < LEXP) g_hist[t] = 0;
    if (t == 0) {
        g_active = 0;
        const unsigned char b0 = mask[0];
        const unsigned char b1 = mask[1];
        g_mask32 = (b0 != 0 && b1 != 0) ? 0 : 1;
    }
}

__device__ __forceinline__ unsigned long long pack2(float lo, float hi) {
    unsigned long long r;
    asm("mov.b64 %0, {%1, %2};" : "=l"(r)
        : "r"(__float_as_uint(lo)), "r"(__float_as_uint(hi)));
    return r;
}

__device__ __forceinline__ void unpack2(unsigned long long v, float& lo, float& hi) {
    unsigned int a, b;
    asm("mov.b64 {%0, %1}, %2;" : "=r"(a), "=r"(b) : "l"(v));
    lo = __uint_as_float(a);
    hi = __uint_as_float(b);
}

// sm_103a packed dual-FMA (FFMA2): 2x fp32 FMA per instruction.
__device__ __forceinline__ unsigned long long ffma2(unsigned long long a,
                                                    unsigned long long b,
                                                    unsigned long long c) {
    unsigned long long d;
    asm("fma.rn.f32x2 %0, %1, %2, %3;" : "=l"(d) : "l"(a), "l"(b), "l"(c));
    return d;
}

__global__ void __launch_bounds__(NTHREADS, 6)
router_kernel(const float* __restrict__ x, const float* __restrict__ Wr,
              const float* __restrict__ bias, const unsigned char* __restrict__ mask,
              float* __restrict__ out_sel, float* __restrict__ out_prob,
              int M, int H)
{
    // sx: [h][token], scalar broadcast reads -> pad 65 (conflict-free stores)
    // sw: [h][permuted expert col], 68-word rows keep 8B alignment for odd h
    __shared__ __align__(16) float sx[HC][TM + 1];
    __shared__ __align__(16) float sw[HC][68];
    __shared__ __align__(16) float slog[TM][LEXP];
    __shared__ float sbias[LEXP];
    __shared__ int   shist[LEXP];
    __shared__ int   sactive;
    __shared__ int   smask32;

    const int tid = threadIdx.x;        // 0..63
    const int tokBase = blockIdx.x * TM;

    sbias[tid] = bias[tid];             // LEXP == NTHREADS == 64
    shist[tid] = 0;
    if (tid == 0) { sactive = 0; smask32 = g_mask32; }

    // compute-tile mapping: 8 tokens x 8 experts (4 expert pairs) per thread
    const int tg = tid >> 3;            // 0..7 -> token group
    const int eg = tid & 7;             // 0..7 -> expert group
    const int tok0 = tg * TT;
    const int e0 = eg * TE;

    // permuted w column for staging: expert e -> word ((e&7)>>1)*16 + (e>>3)*2 + (e&1)
    const int colw = ((tid & 7) >> 1) * 16 + (tid >> 3) * 2 + (tid & 1);

    unsigned long long acc[TT][4];
#pragma unroll
    for (int t = 0; t < TT; ++t)
#pragma unroll
        for (int p = 0; p < 4; ++p) acc[t][p] = 0ULL;

    const int gtok_stage = tokBase + tid;           // token this thread stages
    const float* xrow = x + (size_t)gtok_stage * H;
    const float* wrow = Wr + (size_t)tid * H;       // expert row this thread stages
    const bool xvalid = (gtok_stage < M);

    for (int hb = 0; hb < H; hb += HC) {
        __syncthreads();
        // ---- stage x: thread t = token t, 32 h values ----
        {
            float4 xv[HC / 4];
#pragma unroll
            for (int i = 0; i < HC / 4; ++i)
                xv[i] = xvalid ? *(const float4*)(xrow + hb + i * 4)
                               : make_float4(0.f, 0.f, 0.f, 0.f);
#pragma unroll
            for (int i = 0; i < HC / 4; ++i) {
                sx[i * 4 + 0][tid] = xv[i].x;
                sx[i * 4 + 1][tid] = xv[i].y;
                sx[i * 4 + 2][tid] = xv[i].z;
                sx[i * 4 + 3][tid] = xv[i].w;
            }
        }
        // ---- stage w: thread t = expert t, permuted column ----
        {
            float4 wv[HC / 4];
#pragma unroll
            for (int i = 0; i < HC / 4; ++i)
                wv[i] = *(const float4*)(wrow + hb + i * 4);
#pragma unroll
            for (int i = 0; i < HC / 4; ++i) {
                sw[i * 4 + 0][colw] = wv[i].x;
                sw[i * 4 + 1][colw] = wv[i].y;
                sw[i * 4 + 2][colw] = wv[i].z;
                sw[i * 4 + 3][colw] = wv[i].w;
            }
        }
        __syncthreads();

        // ---- FFMA2 mainloop: 32 ffma2 per thread per h ----
#pragma unroll
        for (int h = 0; h < HC; ++h) {
            // w pairs for this thread: pair p at byte offset p*64 + eg*8
            const char* wbase = (const char*)&sw[h][0] + eg * 8;
            unsigned long long wv[4];
#pragma unroll
            for (int p = 0; p < 4; ++p)
                wv[p] = *(const unsigned long long*)(wbase + p * 64);
#pragma unroll
            for (int t = 0; t < TT; ++t) {
                const float xs = sx[h][tok0 + t];
                const unsigned long long xp = pack2(xs, xs);
#pragma unroll
                for (int p = 0; p < 4; ++p)
                    acc[t][p] = ffma2(xp, wv[p], acc[t][p]);
            }
        }
    }

    // ---- logits to smem (pair p holds experts e0+2p, e0+2p+1) ----
#pragma unroll
    for (int t = 0; t < TT; ++t)
#pragma unroll
        for (int p = 0; p < 4; ++p)
            *(unsigned long long*)&slog[tok0 + t][e0 + 2 * p] = acc[t][p];
    __syncthreads();

    // ---- epilogue: per-token top-8 (logits+bias) + softmax over selected ----
    const int lane = tid & 31;
    const int wrp = tid >> 5;           // 2 warps, 32 tokens each
    const float NEG_INF = -CUDART_INF_F;
    const int mask32 = smask32;

    for (int tk = 0; tk < 32; ++tk) {
        const int tok = wrp * 32 + tk;
        const int gtok = tokBase + tok;
        if (gtok >= M) break;           // uniform within warp

        const float l0 = slog[tok][lane];
        const float l1 = slog[tok][lane + 32];
        float b0 = l0 + sbias[lane];
        float b1 = l1 + sbias[lane + 32];

        int   sel_idx = 0;
        float sel_logit = NEG_INF;

#pragma unroll
        for (int r = 0; r < KSEL; ++r) {
            float bv; int bi;
            if (b0 >= b1) { bv = b0; bi = lane; }       // tie -> lower index
            else          { bv = b1; bi = lane + 32; }
#pragma unroll
            for (int s = 16; s >= 1; s >>= 1) {
                const float ov = __shfl_xor_sync(0xffffffffu, bv, s);
                const int   oi = __shfl_xor_sync(0xffffffffu, bi, s);
                if (ov > bv || (ov == bv && oi < bi)) { bv = ov; bi = oi; }
            }
            if (lane == r) { sel_idx = bi; sel_logit = slog[tok][bi]; }
            if ((bi & 31) == lane) {                    // owner masks winner
                if (bi < 32) b0 = NEG_INF; else b1 = NEG_INF;
            }
        }

        // softmax over the 8 selected unbiased logits (full denom cancels)
        const float lv = (lane < KSEL) ? sel_logit : NEG_INF;
        float mval = lv;
#pragma unroll
        for (int s = 16; s >= 1; s >>= 1)
            mval = fmaxf(mval, __shfl_xor_sync(0xffffffffu, mval, s));
        const float ev = (lane < KSEL) ? __expf(lv - mval) : 0.f;
        float ssum = ev;
#pragma unroll
        for (int s = 16; s >= 1; s >>= 1)
            ssum += __shfl_xor_sync(0xffffffffu, ssum, s);

        bool act;
        if (mask32) act = (((const unsigned int*)mask)[gtok] != 0u);
        else        act = (mask[gtok] != 0);

        if (lane < KSEL) {
            out_sel [(size_t)gtok * KSEL + lane] = (float)sel_idx;
            out_prob[(size_t)gtok * KSEL + lane] = ev / ssum;
            if (act) atomicAdd(&shist[sel_idx], 1);
        }
        if (lane == 0 && act) atomicAdd(&sactive, 1);
    }

    __syncthreads();
    atomicAdd(&g_hist[tid], shist[tid]);
    if (tid == 0) atomicAdd(&g_active, sactive);
}

__global__ void finalize_kernel(float* __restrict__ out_scal, int has_vio) {
    if (threadIdx.x == 0) {
        const float denom = (float)g_active * (float)KSEL;
        const float invL = 1.f / (float)LEXP;
        float s = 0.f, mx = -CUDART_INF_F;
        for (int l = 0; l < LEXP; ++l) {
            const float f = (float)g_hist[l] / denom;
            const float d = f - invL;
            s += d * d;
            mx = fmaxf(mx, d);
        }
        out_scal[0] = (float)LEXP * s;                // load_balance_loss
        if (has_vio) out_scal[1] = (float)LEXP * mx;  // max_vio
    }
}

extern "C" void kernel_launch(void* const* d_in, const int* in_sizes, int n_in,
                              void* d_out, int out_size) {
    const float* x    = (const float*)d_in[0];
    const float* Wr   = (const float*)d_in[1];
    const float* bias = (const float*)d_in[2];
    const unsigned char* mask = (const unsigned char*)d_in[3];

    const int L = in_sizes[2];          // 64
    const int H = in_sizes[1] / L;      // 2048
    const int M = in_sizes[0] / H;      // 16384 tokens (B*N)

    float* out = (float*)d_out;
    float* out_sel  = out;                          // (M, K) indices as float
    float* out_prob = out + (size_t)M * KSEL;       // (M, K) probs
    float* out_scal = out + (size_t)2 * M * KSEL;   // loss [, max_vio]
    const int has_vio = (out_size >= 2 * M * KSEL + 2) ? 1 : 0;

    zero_kernel<<<1, 64>>>(mask);
    const int grid = (M + TM - 1) / TM;
    router_kernel<<<grid, NTHREADS>>>(x, Wr, bias, mask, out_sel, out_prob, M, H);
    finalize_kernel<<<1, 32>>>(out_scal, has_vio);
}

// round 4
// speedup vs baseline: 1.7745x; 1.1204x over previous
#include <cuda_runtime.h>
#include <math_constants.h>

#define LEXP 64
#define KSEL 8
#define TM   112         // tokens per CTA -> grid 147 on M=16384 (one wave on 148 SMs)
#define HC   32          // h-chunk staged in smem
#define NTHREADS 128     // 4 warps -> all 4 SMSPs
#define TT   7           // tokens per thread (16 tg x 8 eg)
#define MAXCTAS 256

#define SX_PAD (TM + 1)  // 113 words per sx row
#define SW_ROW 72        // words per sw row (288B, 16B-aligned)
#define SX_BYTES (HC * SX_PAD * 4)   // 14464
#define SW_BYTES (HC * SW_ROW * 4)   // 9216
#define SLOG_BYTES (TM * LEXP * 4)   // 28672 (>= SX_BYTES+SW_BYTES)

// Per-CTA outputs (overwritten each call -> no zeroing kernel needed).
__device__ int g_hist_cta[MAXCTAS][LEXP];
__device__ int g_act_cta[MAXCTAS];

__device__ __forceinline__ unsigned long long pack2(float lo, float hi) {
    unsigned long long r;
    asm("mov.b64 %0, {%1, %2};" : "=l"(r)
        : "r"(__float_as_uint(lo)), "r"(__float_as_uint(hi)));
    return r;
}

// sm_103a packed dual-FMA (FFMA2): 2x fp32 FMA per instruction.
__device__ __forceinline__ unsigned long long ffma2(unsigned long long a,
                                                    unsigned long long b,
                                                    unsigned long long c) {
    unsigned long long d;
    asm("fma.rn.f32x2 %0, %1, %2, %3;" : "=l"(d) : "l"(a), "l"(b), "l"(c));
    return d;
}

// w swizzle: 16B block index (e>>2) xor'd with (h&7); word = block*4 + (e&3)
__device__ __forceinline__ int w_word(int e, int h) {
    return ((((e >> 2) ^ (h & 7)) << 2) | (e & 3));
}

__global__ void __launch_bounds__(NTHREADS, 1)
router_kernel(const float* __restrict__ x, const float* __restrict__ Wr,
              const float* __restrict__ bias, const unsigned char* __restrict__ mask,
              float* __restrict__ out_sel, float* __restrict__ out_prob,
              int M, int H)
{
    __shared__ __align__(16) unsigned char smem_raw[SLOG_BYTES];
    float (*sx)[SX_PAD]  = (float (*)[SX_PAD])smem_raw;
    float (*sw)[SW_ROW]  = (float (*)[SW_ROW])(smem_raw + SX_BYTES);
    float (*slog)[LEXP]  = (float (*)[LEXP])smem_raw;   // union: reused after mainloop

    __shared__ float sbias[LEXP];
    __shared__ int   shist[LEXP];
    __shared__ int   sactive;
    __shared__ int   smask32;

    const int tid = threadIdx.x;
    const int tokBase = blockIdx.x * TM;

    if (tid < LEXP) { sbias[tid] = bias[tid]; shist[tid] = 0; }
    if (tid == 0) {
        sactive = 0;
        // mask dtype sniff: u8 all-ones -> 01 01; i32 -> 01 00 00 00; f32 -> 00 00 80 3f
        const unsigned char b0 = mask[0];
        const unsigned char b1 = mask[1];
        smask32 = (b0 != 0 && b1 != 0) ? 0 : 1;
    }

    // compute mapping: 16 token-groups x 8 expert-groups
    const int tg = tid >> 3;            // 0..15
    const int eg = tid & 7;             // 0..7
    const int tok0 = tg * TT;
    const int e0 = eg * 8;

    // staging mapping: q-lane coalesced rows
    const int sq = tid & 7;             // 4 floats each, 8 lanes span a 32-float row
    const int srow = tid >> 3;          // 0..15 rows per round

    unsigned long long acc[TT][4];
#pragma unroll
    for (int t = 0; t < TT; ++t)
#pragma unroll
        for (int p = 0; p < 4; ++p) acc[t][p] = 0ULL;

    float4 xr[7], wr[4];
    const int nchunk = H / HC;

    // ---- prologue: prefetch chunk 0 ----
    {
        const int hb = 0;
#pragma unroll
        for (int r = 0; r < 7; ++r) {
            const int gtok = tokBase + r * 16 + srow;
            xr[r] = (gtok < M) ? *(const float4*)(x + (size_t)gtok * H + hb + sq * 4)
                               : make_float4(0.f, 0.f, 0.f, 0.f);
        }
#pragma unroll
        for (int r = 0; r < 4; ++r) {
            const int e = r * 16 + srow;
            wr[r] = *(const float4*)(Wr + (size_t)e * H + hb + sq * 4);
        }
    }

    for (int c = 0; c < nchunk; ++c) {
        __syncthreads();                 // previous compute done -> safe to overwrite
        // ---- store prefetched chunk to smem (transposed) ----
#pragma unroll
        for (int r = 0; r < 7; ++r) {
            const int tk = r * 16 + srow;
            sx[sq * 4 + 0][tk] = xr[r].x;
            sx[sq * 4 + 1][tk] = xr[r].y;
            sx[sq * 4 + 2][tk] = xr[r].z;
            sx[sq * 4 + 3][tk] = xr[r].w;
        }
#pragma unroll
        for (int r = 0; r < 4; ++r) {
            const int e = r * 16 + srow;
            const int h0 = sq * 4;
            sw[h0 + 0][w_word(e, h0 + 0)] = wr[r].x;
            sw[h0 + 1][w_word(e, h0 + 1)] = wr[r].y;
            sw[h0 + 2][w_word(e, h0 + 2)] = wr[r].z;
            sw[h0 + 3][w_word(e, h0 + 3)] = wr[r].w;
        }
        __syncthreads();

        // ---- prefetch next chunk (LDG latency hidden under compute) ----
        if (c + 1 < nchunk) {
            const int hb = (c + 1) * HC;
#pragma unroll
            for (int r = 0; r < 7; ++r) {
                const int gtok = tokBase + r * 16 + srow;
                xr[r] = (gtok < M) ? *(const float4*)(x + (size_t)gtok * H + hb + sq * 4)
                                   : make_float4(0.f, 0.f, 0.f, 0.f);
            }
#pragma unroll
            for (int r = 0; r < 4; ++r) {
                const int e = r * 16 + srow;
                wr[r] = *(const float4*)(Wr + (size_t)e * H + hb + sq * 4);
            }
        }

        // ---- FFMA2 mainloop: 28 ffma2 per thread per h ----
#pragma unroll
        for (int h = 0; h < HC; ++h) {
            const int b0 = ((eg << 1) ^ (h & 7)) << 2;
            const int b1 = (((eg << 1) | 1) ^ (h & 7)) << 2;
            const ulonglong2 wq0 = *(const ulonglong2*)&sw[h][b0];  // experts e0..e0+3
            const ulonglong2 wq1 = *(const ulonglong2*)&sw[h][b1];  // experts e0+4..e0+7
#pragma unroll
            for (int t = 0; t < TT; ++t) {
                const float xs = sx[h][tok0 + t];
                const unsigned long long xp = pack2(xs, xs);
                acc[t][0] = ffma2(xp, wq0.x, acc[t][0]);
                acc[t][1] = ffma2(xp, wq0.y, acc[t][1]);
                acc[t][2] = ffma2(xp, wq1.x, acc[t][2]);
                acc[t][3] = ffma2(xp, wq1.y, acc[t][3]);
            }
        }
    }

    // ---- logits to smem (union with stage buffers; sync first) ----
    __syncthreads();
#pragma unroll
    for (int t = 0; t < TT; ++t)
#pragma unroll
        for (int p = 0; p < 4; ++p)
            *(unsigned long long*)&slog[tok0 + t][e0 + 2 * p] = acc[t][p];
    __syncthreads();

    // ---- epilogue: per-token top-8 (logits+bias) + softmax over selected ----
    const int lane = tid & 31;
    const int wrp = tid >> 5;           // 4 warps, 28 tokens each
    const float NEG_INF = -CUDART_INF_F;
    const int mask32 = smask32;

    for (int tk = 0; tk < TM / 4; ++tk) {
        const int tok = wrp * (TM / 4) + tk;
        const int gtok = tokBase + tok;
        if (gtok >= M) break;           // uniform within warp

        const float l0 = slog[tok][lane];
        const float l1 = slog[tok][lane + 32];
        float b0 = l0 + sbias[lane];
        float b1 = l1 + sbias[lane + 32];

        int   sel_idx = 0;
        float sel_logit = NEG_INF;

#pragma unroll
        for (int r = 0; r < KSEL; ++r) {
            float bv; int bi;
            if (b0 >= b1) { bv = b0; bi = lane; }       // tie -> lower index
            else          { bv = b1; bi = lane + 32; }
#pragma unroll
            for (int s = 16; s >= 1; s >>= 1) {
                const float ov = __shfl_xor_sync(0xffffffffu, bv, s);
                const int   oi = __shfl_xor_sync(0xffffffffu, bi, s);
                if (ov > bv || (ov == bv && oi < bi)) { bv = ov; bi = oi; }
            }
            if (lane == r) { sel_idx = bi; sel_logit = slog[tok][bi]; }
            if ((bi & 31) == lane) {                    // owner masks winner
                if (bi < 32) b0 = NEG_INF; else b1 = NEG_INF;
            }
        }

        // softmax over the 8 selected unbiased logits (full denom cancels)
        const float lv = (lane < KSEL) ? sel_logit : NEG_INF;
        float mval = lv;
#pragma unroll
        for (int s = 16; s >= 1; s >>= 1)
            mval = fmaxf(mval, __shfl_xor_sync(0xffffffffu, mval, s));
        const float ev = (lane < KSEL) ? __expf(lv - mval) : 0.f;
        float ssum = ev;
#pragma unroll
        for (int s = 16; s >= 1; s >>= 1)
            ssum += __shfl_xor_sync(0xffffffffu, ssum, s);

        bool act;
        if (mask32) act = (((const unsigned int*)mask)[gtok] != 0u);
        else        act = (mask[gtok] != 0);

        if (lane < KSEL) {
            out_sel [(size_t)gtok * KSEL + lane] = (float)sel_idx;
            out_prob[(size_t)gtok * KSEL + lane] = ev / ssum;
            if (act) atomicAdd(&shist[sel_idx], 1);
        }
        if (lane == 0 && act) atomicAdd(&sactive, 1);
    }

    __syncthreads();
    if (tid < LEXP) g_hist_cta[blockIdx.x][tid] = shist[tid];
    if (tid == 0)   g_act_cta[blockIdx.x] = sactive;
}

__global__ void finalize_kernel(float* __restrict__ out_scal, int has_vio, int ncta) {
    __shared__ float sd[LEXP];
    __shared__ int   sact;
    const int l = threadIdx.x;          // 64 threads
    int hsum = 0;
    for (int c = 0; c < ncta; ++c) hsum += g_hist_cta[c][l];
    if (l == 0) {
        int a = 0;
        for (int c = 0; c < ncta; ++c) a += g_act_cta[c];
        sact = a;
    }
    __syncthreads();
    const float denom = (float)sact * (float)KSEL;
    const float invL = 1.f / (float)LEXP;
    sd[l] = (float)hsum / denom - invL;
    __syncthreads();
    if (l == 0) {
        float s = 0.f, mx = -CUDART_INF_F;
        for (int e = 0; e < LEXP; ++e) {
            s += sd[e] * sd[e];
            mx = fmaxf(mx, sd[e]);
        }
        out_scal[0] = (float)LEXP * s;                // load_balance_loss
        if (has_vio) out_scal[1] = (float)LEXP * mx;  // max_vio
    }
}

extern "C" void kernel_launch(void* const* d_in, const int* in_sizes, int n_in,
                              void* d_out, int out_size) {
    const float* x    = (const float*)d_in[0];
    const float* Wr   = (const float*)d_in[1];
    const float* bias = (const float*)d_in[2];
    const unsigned char* mask = (const unsigned char*)d_in[3];

    const int L = in_sizes[2];          // 64
    const int H = in_sizes[1] / L;      // 2048
    const int M = in_sizes[0] / H;      // 16384 tokens (B*N)

    float* out = (float*)d_out;
    float* out_sel  = out;                          // (M, K) indices as float
    float* out_prob = out + (size_t)M * KSEL;       // (M, K) probs
    float* out_scal = out + (size_t)2 * M * KSEL;   // loss [, max_vio]
    const int has_vio = (out_size >= 2 * M * KSEL + 2) ? 1 : 0;

    const int grid = (M + TM - 1) / TM;             // 147 for M=16384
    router_kernel<<<grid, NTHREADS>>>(x, Wr, bias, mask, out_sel, out_prob, M, H);
    finalize_kernel<<<1, 64>>>(out_scal, has_vio, grid);
}